// round 1
// baseline (speedup 1.0000x reference)
#include <cuda_runtime.h>

// Problem constants (fixed by the reference)
#define N_NODES 100000
#define N_EDGES 50000
#define M_INC   1600000
#define D       64
#define DC      (D / 4)   // 16 float4 chunks per row

// Scratch (allocation-free rule: __device__ globals)
__device__ float g_Dn[N_NODES];
__device__ float g_Be[N_EDGES];
__device__ float g_edge_feat[(long)N_EDGES * D];
__device__ float g_acc[(long)N_NODES * D];

// ---------------------------------------------------------------------------
// K0: zero all scratch
// ---------------------------------------------------------------------------
__global__ void k_zero() {
    long i = blockIdx.x * (long)blockDim.x + threadIdx.x;
    long stride = (long)gridDim.x * blockDim.x;
    const long EF = (long)N_EDGES * D;
    const long AC = (long)N_NODES * D;
    for (long j = i; j < EF; j += stride) g_edge_feat[j] = 0.f;
    for (long j = i; j < AC; j += stride) g_acc[j] = 0.f;
    for (long j = i; j < N_NODES; j += stride) g_Dn[j] = 0.f;
    for (long j = i; j < N_EDGES; j += stride) g_Be[j] = 0.f;
}

// ---------------------------------------------------------------------------
// K1: node degree Dn (weighted) and edge cardinality Be
// ---------------------------------------------------------------------------
__global__ void k_degree(const int* __restrict__ ni, const int* __restrict__ ei,
                         const float* __restrict__ w) {
    int m = blockIdx.x * blockDim.x + threadIdx.x;
    if (m >= M_INC) return;
    int n = ni[m];
    int e = ei[m];
    atomicAdd(&g_Dn[n], w[e]);
    atomicAdd(&g_Be[e], 1.0f);
}

// ---------------------------------------------------------------------------
// K2: safe reciprocal of Dn and Be (1/v, with v<=0 -> 0)
// ---------------------------------------------------------------------------
__global__ void k_recip() {
    int i = blockIdx.x * blockDim.x + threadIdx.x;
    if (i < N_NODES) {
        float v = g_Dn[i];
        g_Dn[i] = (v > 0.f) ? (1.0f / v) : 0.f;
    }
    if (i < N_EDGES) {
        float v = g_Be[i];
        g_Be[i] = (v > 0.f) ? (1.0f / v) : 0.f;
    }
}

// ---------------------------------------------------------------------------
// K3: stage 1 scatter — edge_feat_raw[e] += x[node]   (vectorized REDG)
// thread t -> (incidence m = t>>4, chunk c = t&15). 16 consecutive threads
// read one 256B x-row coalesced; index loads broadcast in half-warp.
// ---------------------------------------------------------------------------
__global__ void k_stage1(const float* __restrict__ x,
                         const int* __restrict__ ni, const int* __restrict__ ei) {
    long t = blockIdx.x * (long)blockDim.x + threadIdx.x;
    if (t >= (long)M_INC * DC) return;
    int m = (int)(t >> 4);
    int c = (int)(t & 15);
    int n = ni[m];
    int e = ei[m];
    float4 v = ((const float4*)x)[(long)n * DC + c];
    float* dst = &g_edge_feat[(long)e * D + c * 4];
    asm volatile("red.global.add.v4.f32 [%0], {%1,%2,%3,%4};"
                 :: "l"(dst), "f"(v.x), "f"(v.y), "f"(v.z), "f"(v.w)
                 : "memory");
}

// ---------------------------------------------------------------------------
// K4: scale edge_feat by Be (Be is constant per segment, factored out of K3)
// ---------------------------------------------------------------------------
__global__ void k_scale_edges() {
    long t = blockIdx.x * (long)blockDim.x + threadIdx.x;
    if (t >= (long)N_EDGES * D) return;
    g_edge_feat[t] *= g_Be[t >> 6];
}

// ---------------------------------------------------------------------------
// K5: stage 2 scatter — acc[n] += edge_feat[e]   (vectorized REDG)
// ---------------------------------------------------------------------------
__global__ void k_stage2(const int* __restrict__ ni, const int* __restrict__ ei) {
    long t = blockIdx.x * (long)blockDim.x + threadIdx.x;
    if (t >= (long)M_INC * DC) return;
    int m = (int)(t >> 4);
    int c = (int)(t & 15);
    int n = ni[m];
    int e = ei[m];
    float4 v = ((const float4*)g_edge_feat)[(long)e * DC + c];
    float* dst = &g_acc[(long)n * D + c * 4];
    asm volatile("red.global.add.v4.f32 [%0], {%1,%2,%3,%4};"
                 :: "l"(dst), "f"(v.x), "f"(v.y), "f"(v.z), "f"(v.w)
                 : "memory");
}

// ---------------------------------------------------------------------------
// K6: final combine — out = (x + Dn[n] * acc) / 2
// ---------------------------------------------------------------------------
__global__ void k_final(const float* __restrict__ x, float* __restrict__ out) {
    long t = blockIdx.x * (long)blockDim.x + threadIdx.x;
    if (t >= (long)N_NODES * D) return;
    float dn = g_Dn[t >> 6];
    out[t] = 0.5f * (x[t] + dn * g_acc[t]);
}

// ---------------------------------------------------------------------------
extern "C" void kernel_launch(void* const* d_in, const int* in_sizes, int n_in,
                              void* d_out, int out_size) {
    const float* x  = (const float*)d_in[0];
    const int*   ni = (const int*)d_in[1];
    const int*   ei = (const int*)d_in[2];
    const float* w  = (const float*)d_in[3];
    float* out = (float*)d_out;

    const int T = 256;

    // K0: zero scratch
    k_zero<<<2048, T>>>();

    // K1: degrees
    k_degree<<<(M_INC + T - 1) / T, T>>>(ni, ei, w);

    // K2: reciprocals
    k_recip<<<(N_NODES + T - 1) / T, T>>>();

    // K3: stage 1 scatter (nodes -> edges)
    long s1_threads = (long)M_INC * DC;
    k_stage1<<<(int)((s1_threads + T - 1) / T), T>>>(x, ni, ei);

    // K4: scale edge features by Be
    long ef_threads = (long)N_EDGES * D;
    k_scale_edges<<<(int)((ef_threads + T - 1) / T), T>>>();

    // K5: stage 2 scatter (edges -> nodes)
    k_stage2<<<(int)((s1_threads + T - 1) / T), T>>>(ni, ei);

    // K6: final combine
    long out_threads = (long)N_NODES * D;
    k_final<<<(int)((out_threads + T - 1) / T), T>>>(x, out);
}